// round 1
// baseline (speedup 1.0000x reference)
#include <cuda_runtime.h>
#include <cstdint>

#define D       256
#define KMAX    1024
#define NMAX    65536
#define BM      64
#define EPAD    260     // 64-row e tile row stride (floats), %4==0
#define WPAD    68      // w chunk: [16 d][64 codes] padded, %4==0

// -------- device scratch (no allocations allowed) --------
__device__ float        g_nw[KMAX];
__device__ int          g_idx[NMAX];
__device__ unsigned int g_counts[KMAX];
__device__ double       g_loss;

// smem layout for argmin kernel
#define SM_E     (BM * EPAD)                  // 16640 floats
#define SM_W     (16 * WPAD)                  // 1088 floats
#define SM_A     (BM)                         // 64 floats
#define SM_RS    (BM * 16)                    // 1024 floats
#define SM_RI    (BM * 16)                    // 1024 ints
#define SMEM_FLOATS (SM_E + SM_W + SM_A + SM_RS + SM_RI)
#define SMEM_BYTES  (SMEM_FLOATS * 4)

// ---------------------------------------------------------------------------
// Kernel 0: per-code ||w_k||^2 (fp64 accumulate -> fp32), zero accumulators.
// Must run every launch (graph replays!) so counts/loss reset each call.
// ---------------------------------------------------------------------------
__global__ void vq_init_kernel(const float* __restrict__ w, int K) {
    int k = blockIdx.x * blockDim.x + threadIdx.x;
    if (k == 0) g_loss = 0.0;
    if (k < K) {
        const float* wr = w + (size_t)k * D;
        double s = 0.0;
        #pragma unroll 8
        for (int i = 0; i < D; i++) { double v = (double)wr[i]; s += v * v; }
        g_nw[k]     = (float)s;
        g_counts[k] = 0u;
    }
}

// ---------------------------------------------------------------------------
// Kernel 1: fused GEMM + argmin.
// Each block: 64 rows of e (full D in smem), sweeps all K codes.
// Thread (ty=t>>4, tx=t&15) computes a 4-row x 4-code outer product.
// Score replicates jax rounding: s = fp32( fp32(A - 2*dot) + ||w||^2 ),
// tie-break to smallest code index (== jnp.argmin first-occurrence).
// ---------------------------------------------------------------------------
__global__ void __launch_bounds__(256, 2)
vq_argmin_kernel(const float* __restrict__ e, const float* __restrict__ w, int K) {
    extern __shared__ float sm[];
    float* e_s = sm;                    // [BM][EPAD]
    float* w_s = e_s + SM_E;            // [16][WPAD]  (d-major)
    float* A_s = w_s + SM_W;            // [BM]
    float* rs  = A_s + SM_A;            // [BM][16]
    int*   ri  = (int*)(rs + SM_RS);    // [BM][16]

    const int t = threadIdx.x;
    const int rowbase = blockIdx.x * BM;

    // ---- load e tile: thread t -> row t>>2, float4 at d=(t&3)*4 + 16*c ----
    {
        int r  = t >> 2;
        int dv = (t & 3) * 4;
        const float* src = e + (size_t)(rowbase + r) * D;
        #pragma unroll
        for (int c = 0; c < 16; c++) {
            int d = dv + c * 16;
            float4 v = *(const float4*)(src + d);
            *(float4*)(&e_s[r * EPAD + d]) = v;
        }
    }
    __syncthreads();

    // ---- per-row A = ||e_row||^2 (fp64 -> fp32) ----
    if (t < BM) {
        double a = 0.0;
        #pragma unroll 8
        for (int d = 0; d < D; d++) { double v = (double)e_s[t * EPAD + d]; a += v * v; }
        A_s[t] = (float)a;
    }
    // (first __syncthreads in the dc loop orders A_s writes before epilogue reads)

    const int ty = t >> 4;          // row group 0..15  -> rows ty*4 .. ty*4+3
    const int tx = t & 15;          // code group 0..15 -> codes tx*4 .. tx*4+3

    float best[4];
    int   bidx[4];
    #pragma unroll
    for (int i = 0; i < 4; i++) { best[i] = 3.402823e38f; bidx[i] = 0; }

    for (int ct = 0; ct < K; ct += 64) {
        float acc[4][4];
        #pragma unroll
        for (int i = 0; i < 4; i++)
            #pragma unroll
            for (int j = 0; j < 4; j++) acc[i][j] = 0.0f;

        for (int dc = 0; dc < D; dc += 16) {
            __syncthreads();
            // load w chunk: codes [ct, ct+64), d [dc, dc+16) -> w_s[d][code]
            {
                int code = t >> 2;
                int dv   = (t & 3) * 4;
                float4 v = *(const float4*)(w + (size_t)(ct + code) * D + dc + dv);
                w_s[(dv + 0) * WPAD + code] = v.x;
                w_s[(dv + 1) * WPAD + code] = v.y;
                w_s[(dv + 2) * WPAD + code] = v.z;
                w_s[(dv + 3) * WPAD + code] = v.w;
            }
            __syncthreads();

            #pragma unroll
            for (int dd = 0; dd < 16; dd += 4) {
                float4 ev[4], wv[4];
                #pragma unroll
                for (int i = 0; i < 4; i++)
                    ev[i] = *(const float4*)(&e_s[(ty * 4 + i) * EPAD + dc + dd]);
                #pragma unroll
                for (int q = 0; q < 4; q++)
                    wv[q] = *(const float4*)(&w_s[(dd + q) * WPAD + tx * 4]);
                #pragma unroll
                for (int i = 0; i < 4; i++) {
                    float e0 = ev[i].x, e1 = ev[i].y, e2 = ev[i].z, e3 = ev[i].w;
                    acc[i][0] += e0 * wv[0].x; acc[i][1] += e0 * wv[0].y;
                    acc[i][2] += e0 * wv[0].z; acc[i][3] += e0 * wv[0].w;
                    acc[i][0] += e1 * wv[1].x; acc[i][1] += e1 * wv[1].y;
                    acc[i][2] += e1 * wv[1].z; acc[i][3] += e1 * wv[1].w;
                    acc[i][0] += e2 * wv[2].x; acc[i][1] += e2 * wv[2].y;
                    acc[i][2] += e2 * wv[2].z; acc[i][3] += e2 * wv[2].w;
                    acc[i][0] += e3 * wv[3].x; acc[i][1] += e3 * wv[3].y;
                    acc[i][2] += e3 * wv[3].z; acc[i][3] += e3 * wv[3].w;
                }
            }
        }

        // ---- epilogue: score + running argmin ----
        #pragma unroll
        for (int i = 0; i < 4; i++) {
            float A = A_s[ty * 4 + i];
            #pragma unroll
            for (int j = 0; j < 4; j++) {
                int code = ct + tx * 4 + j;
                float nw = __ldg(&g_nw[code]);
                float s  = __fadd_rn(__fadd_rn(A, -2.0f * acc[i][j]), nw);
                if (s < best[i] || (s == best[i] && code < bidx[i])) {
                    best[i] = s; bidx[i] = code;
                }
            }
        }
    }

    // ---- cross-thread (tx) reduction per row, smallest-index tie-break ----
    __syncthreads();
    #pragma unroll
    for (int i = 0; i < 4; i++) {
        rs[(ty * 4 + i) * 16 + tx] = best[i];
        ri[(ty * 4 + i) * 16 + tx] = bidx[i];
    }
    __syncthreads();
    if (t < BM) {
        float b  = rs[t * 16];
        int   bi = ri[t * 16];
        #pragma unroll
        for (int x = 1; x < 16; x++) {
            float s = rs[t * 16 + x];
            int   c = ri[t * 16 + x];
            if (s < b || (s == b && c < bi)) { b = s; bi = c; }
        }
        g_idx[rowbase + t] = bi;
    }
}

// ---------------------------------------------------------------------------
// Kernel 2: gather quantized rows, write indices, accumulate loss + counts.
// One warp per row; 8 rows per 256-thread block; one double atomic per block.
// ---------------------------------------------------------------------------
__global__ void vq_gather_kernel(const float* __restrict__ e,
                                 const float* __restrict__ w,
                                 float* __restrict__ out,
                                 long long out_size, int N) {
    __shared__ double bsum[8];
    const int wl   = threadIdx.x >> 5;
    const int lane = threadIdx.x & 31;
    const int row  = blockIdx.x * 8 + wl;

    float ss = 0.0f;
    int idx = 0;
    if (row < N) {
        idx = g_idx[row];
        const float4* qp = (const float4*)(w + (size_t)idx * D);
        const float4* ep = (const float4*)(e + (size_t)row * D);
        float4*       op = (float4*)(out + (size_t)row * D);
        #pragma unroll
        for (int c = 0; c < 2; c++) {
            int i = lane + c * 32;          // 64 float4 per row
            float4 q  = __ldg(&qp[i]);
            float4 ev = ep[i];
            op[i] = q;
            float dx = q.x - ev.x, dy = q.y - ev.y;
            float dz = q.z - ev.z, dw = q.w - ev.w;
            ss += dx * dx + dy * dy + dz * dz + dw * dw;
        }
    }
    // warp reduce
    #pragma unroll
    for (int o = 16; o; o >>= 1) ss += __shfl_xor_sync(0xffffffffu, ss, o);
    if (lane == 0) {
        bsum[wl] = (double)ss;
        if (row < N) {
            atomicAdd(&g_counts[idx], 1u);
            long long p = (long long)N * D + row;
            if (p < out_size) out[p] = (float)idx;
        }
    }
    __syncthreads();
    if (threadIdx.x == 0) {
        double s = 0.0;
        #pragma unroll
        for (int i = 0; i < 8; i++) s += bsum[i];
        atomicAdd(&g_loss, s);
    }
}

// ---------------------------------------------------------------------------
// Kernel 3: finalize scalars: commitment_loss, codebook_usage.
// ---------------------------------------------------------------------------
__global__ void vq_finalize_kernel(float* __restrict__ out, long long out_size,
                                   int N, int K) {
    __shared__ unsigned red[1024];
    int t = threadIdx.x;
    unsigned m = (t < K) ? g_counts[t] : 0u;
    red[t] = m;
    __syncthreads();
    #pragma unroll
    for (int s = 512; s; s >>= 1) {
        if (t < s) { unsigned o = red[t + s]; if (o > red[t]) red[t] = o; }
        __syncthreads();
    }
    if (t == 0) {
        long long base = (long long)N * D + N;
        if (base < out_size)
            out[base] = (float)(g_loss / ((double)N * (double)D));
        if (base + 1 < out_size)
            out[base + 1] = (float)red[0] / (float)N;
    }
}

// ---------------------------------------------------------------------------
extern "C" void kernel_launch(void* const* d_in, const int* in_sizes, int n_in,
                              void* d_out, int out_size) {
    const float* e = (const float*)d_in[0];
    const float* w = (const float*)d_in[1];
    float* out = (float*)d_out;

    int N = in_sizes[0] / D;
    int K = in_sizes[1] / D;
    if (N > NMAX) N = NMAX;
    if (K > KMAX) K = KMAX;
    long long osz = (long long)out_size;

    cudaFuncSetAttribute(vq_argmin_kernel,
                         cudaFuncAttributeMaxDynamicSharedMemorySize, SMEM_BYTES);

    vq_init_kernel<<<(K + 255) / 256, 256>>>(w, K);
    vq_argmin_kernel<<<N / BM, 256, SMEM_BYTES>>>(e, w, K);
    vq_gather_kernel<<<(N + 7) / 8, 256>>>(e, w, out, osz, N);
    vq_finalize_kernel<<<1, 1024>>>(out, osz, N, K);
}

// round 4
// speedup vs baseline: 1.5414x; 1.5414x over previous
#include <cuda_runtime.h>
#include <cuda_bf16.h>
#include <cstdint>
#include <cfloat>

#define D       256
#define KMAX    1024
#define NMAX    65536
#define BM      128
#define ESTR    264     // bf16 stride for e smem tiles
#define WSTR    72      // bf16 stride for w smem chunks
#define DCH     64
#define RESCUE_THRESH 5e-5f

// -------- device scratch (static; no runtime allocation) --------
__device__ __nv_bfloat16 g_ehi[(size_t)NMAX * D];
__device__ __nv_bfloat16 g_elo[(size_t)NMAX * D];
__device__ __nv_bfloat16 g_whi[(size_t)KMAX * D];
__device__ __nv_bfloat16 g_wlo[(size_t)KMAX * D];
__device__ float        g_nw[KMAX];
__device__ float        g_A[NMAX];
__device__ int          g_idx[NMAX];
__device__ unsigned int g_counts[KMAX];
__device__ double       g_loss;
__device__ int          g_flagcnt;
__device__ int          g_flaglist[NMAX];

// smem layout for the mma argmin kernel (bytes)
#define SM_EHI_B   (BM * ESTR * 2)
#define SM_WBUF_B  (2 * BM * WSTR * 2)
#define SMEM_BYTES (2 * SM_EHI_B + SM_WBUF_B + BM * 4 + KMAX * 4 \
                    + BM * 2 * 4 + BM * 2 * 4 + BM * 2 * 4)

// ---------------------------------------------------------------------------
// helpers
// ---------------------------------------------------------------------------
__device__ __forceinline__ void cpa16(void* dst, const void* src) {
    unsigned d = (unsigned)__cvta_generic_to_shared(dst);
    asm volatile("cp.async.cg.shared.global [%0], [%1], 16;\n" :: "r"(d), "l"(src));
}
__device__ __forceinline__ void cpa_commit() {
    asm volatile("cp.async.commit_group;\n");
}
__device__ __forceinline__ void cpa_wait0() {
    asm volatile("cp.async.wait_group 0;\n");
}
__device__ __forceinline__ void mma_bf16(float* c, const unsigned* a, unsigned b0, unsigned b1) {
    asm volatile(
        "mma.sync.aligned.m16n8k16.row.col.f32.bf16.bf16.f32 "
        "{%0,%1,%2,%3}, {%4,%5,%6,%7}, {%8,%9}, {%0,%1,%2,%3};\n"
        : "+f"(c[0]), "+f"(c[1]), "+f"(c[2]), "+f"(c[3])
        : "r"(a[0]), "r"(a[1]), "r"(a[2]), "r"(a[3]), "r"(b0), "r"(b1));
}

// ---------------------------------------------------------------------------
// Kernel: convert e -> bf16 hi/lo, compute ||e_row||^2 (fp64 -> fp32).
// ---------------------------------------------------------------------------
__global__ void vq_prep_e(const float* __restrict__ e, int N) {
    int gw   = (blockIdx.x * blockDim.x + threadIdx.x) >> 5;
    int lane = threadIdx.x & 31;
    if (gw >= N) return;
    const float* src = e + (size_t)gw * D + lane * 8;
    float4 v0 = *(const float4*)(src);
    float4 v1 = *(const float4*)(src + 4);
    float x[8] = {v0.x, v0.y, v0.z, v0.w, v1.x, v1.y, v1.z, v1.w};
    double s = 0.0;
    unsigned hi[4], lo[4];
    #pragma unroll
    for (int i = 0; i < 4; i++) {
        float a = x[2*i], b = x[2*i+1];
        s += (double)a * a + (double)b * b;
        __nv_bfloat16 ha = __float2bfloat16_rn(a);
        __nv_bfloat16 hb = __float2bfloat16_rn(b);
        __nv_bfloat16 la = __float2bfloat16_rn(a - __bfloat162float(ha));
        __nv_bfloat16 lb = __float2bfloat16_rn(b - __bfloat162float(hb));
        hi[i] = (unsigned)__bfloat16_as_ushort(ha) | ((unsigned)__bfloat16_as_ushort(hb) << 16);
        lo[i] = (unsigned)__bfloat16_as_ushort(la) | ((unsigned)__bfloat16_as_ushort(lb) << 16);
    }
    *(uint4*)(g_ehi + (size_t)gw * D + lane * 8) = make_uint4(hi[0], hi[1], hi[2], hi[3]);
    *(uint4*)(g_elo + (size_t)gw * D + lane * 8) = make_uint4(lo[0], lo[1], lo[2], lo[3]);
    #pragma unroll
    for (int o = 16; o; o >>= 1) s += __shfl_xor_sync(0xffffffffu, s, o);
    if (lane == 0) g_A[gw] = (float)s;
}

// ---------------------------------------------------------------------------
// Kernel: convert w -> bf16 hi/lo, ||w_k||^2, zero counts/loss/flags.
// ---------------------------------------------------------------------------
__global__ void vq_prep_w(const float* __restrict__ w, int K) {
    int gid  = blockIdx.x * blockDim.x + threadIdx.x;
    int gw   = gid >> 5;
    int lane = threadIdx.x & 31;
    if (gid < K)  g_counts[gid] = 0u;
    if (gid == 0) { g_loss = 0.0; g_flagcnt = 0; }
    if (gw >= K) return;
    const float* src = w + (size_t)gw * D + lane * 8;
    float4 v0 = *(const float4*)(src);
    float4 v1 = *(const float4*)(src + 4);
    float x[8] = {v0.x, v0.y, v0.z, v0.w, v1.x, v1.y, v1.z, v1.w};
    double s = 0.0;
    unsigned hi[4], lo[4];
    #pragma unroll
    for (int i = 0; i < 4; i++) {
        float a = x[2*i], b = x[2*i+1];
        s += (double)a * a + (double)b * b;
        __nv_bfloat16 ha = __float2bfloat16_rn(a);
        __nv_bfloat16 hb = __float2bfloat16_rn(b);
        __nv_bfloat16 la = __float2bfloat16_rn(a - __bfloat162float(ha));
        __nv_bfloat16 lb = __float2bfloat16_rn(b - __bfloat162float(hb));
        hi[i] = (unsigned)__bfloat16_as_ushort(ha) | ((unsigned)__bfloat16_as_ushort(hb) << 16);
        lo[i] = (unsigned)__bfloat16_as_ushort(la) | ((unsigned)__bfloat16_as_ushort(lb) << 16);
    }
    *(uint4*)(g_whi + (size_t)gw * D + lane * 8) = make_uint4(hi[0], hi[1], hi[2], hi[3]);
    *(uint4*)(g_wlo + (size_t)gw * D + lane * 8) = make_uint4(lo[0], lo[1], lo[2], lo[3]);
    #pragma unroll
    for (int o = 16; o; o >>= 1) s += __shfl_xor_sync(0xffffffffu, s, o);
    if (lane == 0) g_nw[gw] = (float)s;
}

// ---------------------------------------------------------------------------
// Kernel: fused split-bf16 HMMA GEMM + top-2 argmin + near-tie flagging.
// ---------------------------------------------------------------------------
__device__ __forceinline__ void load_w_chunk(__nv_bfloat16* wb,
                                             const __nv_bfloat16* src,
                                             int ct, int dc, int t) {
    #pragma unroll
    for (int i = 0; i < 4; i++) {
        int id = t + i * 256;
        int code = id >> 3;
        int dcol = (id & 7) * 8;
        cpa16(wb + code * WSTR + dcol,
              src + (size_t)(ct * BM + code) * D + dc + dcol);
    }
    cpa_commit();
}

__global__ void __launch_bounds__(256, 1)
vq_argmin_mma(int K) {
    extern __shared__ char smraw[];
    __nv_bfloat16* ehi_s = (__nv_bfloat16*)smraw;
    __nv_bfloat16* elo_s = ehi_s + BM * ESTR;
    __nv_bfloat16* wbuf  = elo_s + BM * ESTR;
    float* A_s  = (float*)(wbuf + 2 * BM * WSTR);
    float* nw_s = A_s + BM;
    float* rS   = nw_s + KMAX;
    float* rC   = rS + BM * 2;                   // second-best
    int*   rI   = (int*)(rC + BM * 2);

    const int t    = threadIdx.x;
    const int lane = t & 31;
    const int wid  = t >> 5;
    const int wrow = wid >> 1;
    const int wcol = wid & 1;
    const int rowbase = blockIdx.x * BM;
    const int lr = lane >> 2;
    const int lk = (lane & 3) * 2;

    {
        const __nv_bfloat16* sh = g_ehi + (size_t)rowbase * D;
        const __nv_bfloat16* sl = g_elo + (size_t)rowbase * D;
        #pragma unroll
        for (int i = 0; i < 16; i++) {
            int id = t + i * 256;
            int r = id >> 5, dc = (id & 31) * 8;
            *(uint4*)(ehi_s + r * ESTR + dc) = *(const uint4*)(sh + r * D + dc);
            *(uint4*)(elo_s + r * ESTR + dc) = *(const uint4*)(sl + r * D + dc);
        }
    }
    if (t < BM) A_s[t] = g_A[rowbase + t];
    #pragma unroll
    for (int i = 0; i < 4; i++) nw_s[t + i * 256] = g_nw[t + i * 256];
    __syncthreads();

    float best[4], sec[4];
    int   bidx[4];
    #pragma unroll
    for (int i = 0; i < 4; i++) { best[i] = FLT_MAX; sec[i] = FLT_MAX; bidx[i] = 0; }

    for (int ct = 0; ct < K / BM; ct++) {
        float acc[2][8][4];
        #pragma unroll
        for (int mf = 0; mf < 2; mf++)
            #pragma unroll
            for (int nf = 0; nf < 8; nf++)
                #pragma unroll
                for (int v = 0; v < 4; v++) acc[mf][nf][v] = 0.0f;

        load_w_chunk(wbuf, g_whi, ct, 0, t);

        for (int step = 0; step < 12; step++) {
            cpa_wait0();
            __syncthreads();
            if (step < 11) {
                int ns = step + 1;
                const __nv_bfloat16* src = ((ns >> 2) == 1) ? g_wlo : g_whi;
                load_w_chunk(wbuf + (ns & 1) * (BM * WSTR), src, ct,
                             (ns & 3) * DCH, t);
            }
            const __nv_bfloat16* eS = (step >= 8) ? elo_s : ehi_s;
            const __nv_bfloat16* wS = wbuf + (step & 1) * (BM * WSTR);
            const int dc = (step & 3) * DCH;

            #pragma unroll
            for (int ks = 0; ks < 4; ks++) {
                const int k0 = dc + ks * 16 + lk;
                const int kl = ks * 16 + lk;
                unsigned a[2][4];
                #pragma unroll
                for (int mf = 0; mf < 2; mf++) {
                    int r = wrow * 32 + mf * 16 + lr;
                    a[mf][0] = *(const unsigned*)(eS + r * ESTR + k0);
                    a[mf][1] = *(const unsigned*)(eS + (r + 8) * ESTR + k0);
                    a[mf][2] = *(const unsigned*)(eS + r * ESTR + k0 + 8);
                    a[mf][3] = *(const unsigned*)(eS + (r + 8) * ESTR + k0 + 8);
                }
                #pragma unroll
                for (int nf = 0; nf < 8; nf++) {
                    int c = wcol * 64 + nf * 8 + lr;
                    unsigned b0 = *(const unsigned*)(wS + c * WSTR + kl);
                    unsigned b1 = *(const unsigned*)(wS + c * WSTR + kl + 8);
                    mma_bf16(acc[0][nf], a[0], b0, b1);
                    mma_bf16(acc[1][nf], a[1], b0, b1);
                }
            }
        }

        // ---- epilogue: score + running top-2 ----
        #pragma unroll
        for (int mf = 0; mf < 2; mf++)
        #pragma unroll
        for (int rh = 0; rh < 2; rh++) {
            const int slot = mf * 2 + rh;
            float A = A_s[wrow * 32 + mf * 16 + rh * 8 + lr];
            #pragma unroll
            for (int nf = 0; nf < 8; nf++)
            #pragma unroll
            for (int ci = 0; ci < 2; ci++) {
                int code = ct * BM + wcol * 64 + nf * 8 + (lane & 3) * 2 + ci;
                float dot = acc[mf][nf][rh * 2 + ci];
                float s = __fadd_rn(__fadd_rn(A, -2.0f * dot), nw_s[code]);
                if (s < best[slot] || (s == best[slot] && code < bidx[slot])) {
                    sec[slot]  = best[slot];
                    best[slot] = s; bidx[slot] = code;
                } else if (s < sec[slot]) {
                    sec[slot] = s;
                }
            }
        }
    }

    // ---- cross-lane top-2 merge (lanes sharing a row differ in lane&3) ----
    #pragma unroll
    for (int slot = 0; slot < 4; slot++) {
        #pragma unroll
        for (int o = 1; o < 4; o <<= 1) {
            float ob = __shfl_xor_sync(0xffffffffu, best[slot], o);
            float os = __shfl_xor_sync(0xffffffffu, sec[slot], o);
            int   oi = __shfl_xor_sync(0xffffffffu, bidx[slot], o);
            if (ob < best[slot] || (ob == best[slot] && oi < bidx[slot])) {
                sec[slot]  = fminf(best[slot], os);
                best[slot] = ob; bidx[slot] = oi;
            } else {
                sec[slot] = fminf(sec[slot], ob);
            }
        }
    }
    if ((lane & 3) == 0) {
        #pragma unroll
        for (int slot = 0; slot < 4; slot++) {
            int mf = slot >> 1, rh = slot & 1;
            int row = wrow * 32 + mf * 16 + rh * 8 + lr;
            rS[row * 2 + wcol] = best[slot];
            rC[row * 2 + wcol] = sec[slot];
            rI[row * 2 + wcol] = bidx[slot];
        }
    }
    __syncthreads();
    if (t < BM) {
        float b0 = rS[t * 2 + 0], b1 = rS[t * 2 + 1];
        float c0 = rC[t * 2 + 0], c1 = rC[t * 2 + 1];
        int   i0 = rI[t * 2 + 0], i1 = rI[t * 2 + 1];
        float fb, fs; int fi;
        if (b1 < b0 || (b1 == b0 && i1 < i0)) {
            fb = b1; fi = i1; fs = fminf(b0, c1);
        } else {
            fb = b0; fi = i0; fs = fminf(c0, b1);
        }
        g_idx[rowbase + t] = fi;
        if (fs - fb < RESCUE_THRESH) {
            int pos = atomicAdd(&g_flagcnt, 1);
            if (pos < NMAX) g_flaglist[pos] = rowbase + t;
        }
    }
}

// ---------------------------------------------------------------------------
// Kernel: exact fp32 rescore of flagged (near-tie) rows. Warp per row,
// 8 rows per block, grid-stride over the flag list.
// ---------------------------------------------------------------------------
__global__ void __launch_bounds__(256)
vq_rescue(const float* __restrict__ e, const float* __restrict__ w, int K) {
    const int wid  = threadIdx.x >> 5;
    const int lane = threadIdx.x & 31;
    const int nflag = g_flagcnt;
    for (int base = blockIdx.x * 8; base < nflag; base += gridDim.x * 8) {
        int slot = base + wid;
        if (slot >= nflag) continue;
        int row = g_flaglist[slot];
        const float* er = e + (size_t)row * D + lane * 8;
        float4 v0 = *(const float4*)er;
        float4 v1 = *(const float4*)(er + 4);
        float A = g_A[row];
        float best = FLT_MAX; int bidx = 0;
        for (int c = 0; c < K; c++) {
            const float4* wr = (const float4*)(w + (size_t)c * D + lane * 8);
            float4 w0 = __ldg(wr), w1 = __ldg(wr + 1);
            float d = v0.x * w0.x + v0.y * w0.y + v0.z * w0.z + v0.w * w0.w
                    + v1.x * w1.x + v1.y * w1.y + v1.z * w1.z + v1.w * w1.w;
            #pragma unroll
            for (int o = 16; o; o >>= 1) d += __shfl_xor_sync(0xffffffffu, d, o);
            float s = __fadd_rn(__fadd_rn(A, -2.0f * d), __ldg(&g_nw[c]));
            if (s < best) { best = s; bidx = c; }   // ascending c => first-index tie-break
        }
        if (lane == 0) g_idx[row] = bidx;
    }
}

// ---------------------------------------------------------------------------
// Kernel: gather quantized rows, write indices, accumulate loss + counts.
// ---------------------------------------------------------------------------
__global__ void vq_gather_kernel(const float* __restrict__ e,
                                 const float* __restrict__ w,
                                 float* __restrict__ out,
                                 long long out_size, int N) {
    __shared__ double bsum[8];
    const int wl   = threadIdx.x >> 5;
    const int lane = threadIdx.x & 31;
    const int row  = blockIdx.x * 8 + wl;

    float ss = 0.0f;
    int idx = 0;
    if (row < N) {
        idx = g_idx[row];
        const float4* qp = (const float4*)(w + (size_t)idx * D);
        const float4* ep = (const float4*)(e + (size_t)row * D);
        float4*       op = (float4*)(out + (size_t)row * D);
        #pragma unroll
        for (int c = 0; c < 2; c++) {
            int i = lane + c * 32;
            float4 q  = __ldg(&qp[i]);
            float4 ev = ep[i];
            op[i] = q;
            float dx = q.x - ev.x, dy = q.y - ev.y;
            float dz = q.z - ev.z, dw = q.w - ev.w;
            ss += dx * dx + dy * dy + dz * dz + dw * dw;
        }
    }
    #pragma unroll
    for (int o = 16; o; o >>= 1) ss += __shfl_xor_sync(0xffffffffu, ss, o);
    if (lane == 0) {
        bsum[wl] = (double)ss;
        if (row < N) {
            atomicAdd(&g_counts[idx], 1u);
            long long p = (long long)N * D + row;
            if (p < out_size) out[p] = (float)idx;
        }
    }
    __syncthreads();
    if (threadIdx.x == 0) {
        double s = 0.0;
        #pragma unroll
        for (int i = 0; i < 8; i++) s += bsum[i];
        atomicAdd(&g_loss, s);
    }
}

// ---------------------------------------------------------------------------
// Kernel: finalize scalars.
// ---------------------------------------------------------------------------
__global__ void vq_finalize_kernel(float* __restrict__ out, long long out_size,
                                   int N, int K) {
    __shared__ unsigned red[1024];
    int t = threadIdx.x;
    unsigned m = (t < K) ? g_counts[t] : 0u;
    red[t] = m;
    __syncthreads();
    #pragma unroll
    for (int s = 512; s; s >>= 1) {
        if (t < s) { unsigned o = red[t + s]; if (o > red[t]) red[t] = o; }
        __syncthreads();
    }
    if (t == 0) {
        long long base = (long long)N * D + N;
        if (base < out_size)
            out[base] = (float)(g_loss / ((double)N * (double)D));
        if (base + 1 < out_size)
            out[base + 1] = (float)red[0] / (float)N;
    }
}

// ---------------------------------------------------------------------------
extern "C" void kernel_launch(void* const* d_in, const int* in_sizes, int n_in,
                              void* d_out, int out_size) {
    const float* e = (const float*)d_in[0];
    const float* w = (const float*)d_in[1];
    float* out = (float*)d_out;

    int N = in_sizes[0] / D;
    int K = in_sizes[1] / D;
    if (N > NMAX) N = NMAX;
    if (K > KMAX) K = KMAX;
    long long osz = (long long)out_size;

    cudaFuncSetAttribute(vq_argmin_mma,
                         cudaFuncAttributeMaxDynamicSharedMemorySize, SMEM_BYTES);

    vq_prep_e<<<(N * 32 + 255) / 256, 256>>>(e, N);
    vq_prep_w<<<(K * 32 + 255) / 256, 256>>>(w, K);
    vq_argmin_mma<<<N / BM, 256, SMEM_BYTES>>>(K);
    vq_rescue<<<512, 256>>>(e, w, K);
    vq_gather_kernel<<<(N + 7) / 8, 256>>>(e, w, out, osz, N);
    vq_finalize_kernel<<<1, 1024>>>(out, osz, N, K);
}

// round 5
// speedup vs baseline: 1.8754x; 1.2167x over previous
#include <cuda_runtime.h>
#include <cuda_bf16.h>
#include <cstdint>
#include <cfloat>

#define D       256
#define KMAX    1024
#define NMAX    65536
#define BM      128
#define ESTR    264     // bf16 stride for e smem tiles
#define WSTR    72      // bf16 stride for w smem chunks
#define DCH     64
#define RESCUE_THRESH 5e-5f

// -------- device scratch (static; no runtime allocation) --------
__device__ __nv_bfloat16 g_ehi[(size_t)NMAX * D];
__device__ __nv_bfloat16 g_elo[(size_t)NMAX * D];
__device__ __nv_bfloat16 g_whi[(size_t)KMAX * D];
__device__ __nv_bfloat16 g_wlo[(size_t)KMAX * D];
__device__ float        g_nw[KMAX];
__device__ float        g_A[NMAX];
__device__ int          g_idx[NMAX];
__device__ unsigned int g_counts[KMAX];
__device__ double       g_loss;
__device__ int          g_flagcnt;
__device__ int          g_flaglist[NMAX];

// smem layout for the mma argmin kernel (bytes)
#define SM_EHI_B   (BM * ESTR * 2)
#define SM_WBUF_B  (2 * BM * WSTR * 2)
#define SMEM_BYTES (2 * SM_EHI_B + SM_WBUF_B + BM * 4 + KMAX * 4 \
                    + BM * 2 * 4 + BM * 2 * 4 + BM * 2 * 4)

// ---------------------------------------------------------------------------
// helpers
// ---------------------------------------------------------------------------
__device__ __forceinline__ void cpa16(void* dst, const void* src) {
    unsigned d = (unsigned)__cvta_generic_to_shared(dst);
    asm volatile("cp.async.cg.shared.global [%0], [%1], 16;\n" :: "r"(d), "l"(src));
}
__device__ __forceinline__ void cpa_commit() {
    asm volatile("cp.async.commit_group;\n");
}
__device__ __forceinline__ void cpa_wait0() {
    asm volatile("cp.async.wait_group 0;\n");
}
__device__ __forceinline__ void mma_bf16(float* c, const unsigned* a, unsigned b0, unsigned b1) {
    asm volatile(
        "mma.sync.aligned.m16n8k16.row.col.f32.bf16.bf16.f32 "
        "{%0,%1,%2,%3}, {%4,%5,%6,%7}, {%8,%9}, {%0,%1,%2,%3};\n"
        : "+f"(c[0]), "+f"(c[1]), "+f"(c[2]), "+f"(c[3])
        : "r"(a[0]), "r"(a[1]), "r"(a[2]), "r"(a[3]), "r"(b0), "r"(b1));
}

// ---------------------------------------------------------------------------
// Kernel: convert e -> bf16 hi/lo, compute ||e_row||^2 (fp64 -> fp32).
// ---------------------------------------------------------------------------
__global__ void vq_prep_e(const float* __restrict__ e, int N) {
    int gw   = (blockIdx.x * blockDim.x + threadIdx.x) >> 5;
    int lane = threadIdx.x & 31;
    if (gw >= N) return;
    const float* src = e + (size_t)gw * D + lane * 8;
    float4 v0 = *(const float4*)(src);
    float4 v1 = *(const float4*)(src + 4);
    float x[8] = {v0.x, v0.y, v0.z, v0.w, v1.x, v1.y, v1.z, v1.w};
    double s = 0.0;
    unsigned hi[4], lo[4];
    #pragma unroll
    for (int i = 0; i < 4; i++) {
        float a = x[2*i], b = x[2*i+1];
        s += (double)a * a + (double)b * b;
        __nv_bfloat16 ha = __float2bfloat16_rn(a);
        __nv_bfloat16 hb = __float2bfloat16_rn(b);
        __nv_bfloat16 la = __float2bfloat16_rn(a - __bfloat162float(ha));
        __nv_bfloat16 lb = __float2bfloat16_rn(b - __bfloat162float(hb));
        hi[i] = (unsigned)__bfloat16_as_ushort(ha) | ((unsigned)__bfloat16_as_ushort(hb) << 16);
        lo[i] = (unsigned)__bfloat16_as_ushort(la) | ((unsigned)__bfloat16_as_ushort(lb) << 16);
    }
    *(uint4*)(g_ehi + (size_t)gw * D + lane * 8) = make_uint4(hi[0], hi[1], hi[2], hi[3]);
    *(uint4*)(g_elo + (size_t)gw * D + lane * 8) = make_uint4(lo[0], lo[1], lo[2], lo[3]);
    #pragma unroll
    for (int o = 16; o; o >>= 1) s += __shfl_xor_sync(0xffffffffu, s, o);
    if (lane == 0) g_A[gw] = (float)s;
}

// ---------------------------------------------------------------------------
// Kernel: convert w -> bf16 hi/lo, ||w_k||^2, zero counts/loss/flags.
// ---------------------------------------------------------------------------
__global__ void vq_prep_w(const float* __restrict__ w, int K) {
    int gid  = blockIdx.x * blockDim.x + threadIdx.x;
    int gw   = gid >> 5;
    int lane = threadIdx.x & 31;
    if (gid < K)  g_counts[gid] = 0u;
    if (gid == 0) { g_loss = 0.0; g_flagcnt = 0; }
    if (gw >= K) return;
    const float* src = w + (size_t)gw * D + lane * 8;
    float4 v0 = *(const float4*)(src);
    float4 v1 = *(const float4*)(src + 4);
    float x[8] = {v0.x, v0.y, v0.z, v0.w, v1.x, v1.y, v1.z, v1.w};
    double s = 0.0;
    unsigned hi[4], lo[4];
    #pragma unroll
    for (int i = 0; i < 4; i++) {
        float a = x[2*i], b = x[2*i+1];
        s += (double)a * a + (double)b * b;
        __nv_bfloat16 ha = __float2bfloat16_rn(a);
        __nv_bfloat16 hb = __float2bfloat16_rn(b);
        __nv_bfloat16 la = __float2bfloat16_rn(a - __bfloat162float(ha));
        __nv_bfloat16 lb = __float2bfloat16_rn(b - __bfloat162float(hb));
        hi[i] = (unsigned)__bfloat16_as_ushort(ha) | ((unsigned)__bfloat16_as_ushort(hb) << 16);
        lo[i] = (unsigned)__bfloat16_as_ushort(la) | ((unsigned)__bfloat16_as_ushort(lb) << 16);
    }
    *(uint4*)(g_whi + (size_t)gw * D + lane * 8) = make_uint4(hi[0], hi[1], hi[2], hi[3]);
    *(uint4*)(g_wlo + (size_t)gw * D + lane * 8) = make_uint4(lo[0], lo[1], lo[2], lo[3]);
    #pragma unroll
    for (int o = 16; o; o >>= 1) s += __shfl_xor_sync(0xffffffffu, s, o);
    if (lane == 0) g_nw[gw] = (float)s;
}

// ---------------------------------------------------------------------------
// Kernel: fused split-bf16 HMMA GEMM + top-2 argmin + near-tie flagging.
// ---------------------------------------------------------------------------
__device__ __forceinline__ void load_w_chunk(__nv_bfloat16* wb,
                                             const __nv_bfloat16* src,
                                             int ct, int dc, int t) {
    #pragma unroll
    for (int i = 0; i < 4; i++) {
        int id = t + i * 256;
        int code = id >> 3;
        int dcol = (id & 7) * 8;
        cpa16(wb + code * WSTR + dcol,
              src + (size_t)(ct * BM + code) * D + dc + dcol);
    }
    cpa_commit();
}

__global__ void __launch_bounds__(256, 1)
vq_argmin_mma(int K) {
    extern __shared__ char smraw[];
    __nv_bfloat16* ehi_s = (__nv_bfloat16*)smraw;
    __nv_bfloat16* elo_s = ehi_s + BM * ESTR;
    __nv_bfloat16* wbuf  = elo_s + BM * ESTR;
    float* A_s  = (float*)(wbuf + 2 * BM * WSTR);
    float* nw_s = A_s + BM;
    float* rS   = nw_s + KMAX;
    float* rC   = rS + BM * 2;                   // second-best
    int*   rI   = (int*)(rC + BM * 2);

    const int t    = threadIdx.x;
    const int lane = t & 31;
    const int wid  = t >> 5;
    const int wrow = wid >> 1;
    const int wcol = wid & 1;
    const int rowbase = blockIdx.x * BM;
    const int lr = lane >> 2;
    const int lk = (lane & 3) * 2;

    {
        const __nv_bfloat16* sh = g_ehi + (size_t)rowbase * D;
        const __nv_bfloat16* sl = g_elo + (size_t)rowbase * D;
        #pragma unroll
        for (int i = 0; i < 16; i++) {
            int id = t + i * 256;
            int r = id >> 5, dc = (id & 31) * 8;
            *(uint4*)(ehi_s + r * ESTR + dc) = *(const uint4*)(sh + r * D + dc);
            *(uint4*)(elo_s + r * ESTR + dc) = *(const uint4*)(sl + r * D + dc);
        }
    }
    if (t < BM) A_s[t] = g_A[rowbase + t];
    #pragma unroll
    for (int i = 0; i < 4; i++) nw_s[t + i * 256] = g_nw[t + i * 256];
    __syncthreads();

    float best[4], sec[4];
    int   bidx[4];
    #pragma unroll
    for (int i = 0; i < 4; i++) { best[i] = FLT_MAX; sec[i] = FLT_MAX; bidx[i] = 0; }

    for (int ct = 0; ct < K / BM; ct++) {
        float acc[2][8][4];
        #pragma unroll
        for (int mf = 0; mf < 2; mf++)
            #pragma unroll
            for (int nf = 0; nf < 8; nf++)
                #pragma unroll
                for (int v = 0; v < 4; v++) acc[mf][nf][v] = 0.0f;

        load_w_chunk(wbuf, g_whi, ct, 0, t);

        for (int step = 0; step < 12; step++) {
            cpa_wait0();
            __syncthreads();
            if (step < 11) {
                int ns = step + 1;
                const __nv_bfloat16* src = ((ns >> 2) == 1) ? g_wlo : g_whi;
                load_w_chunk(wbuf + (ns & 1) * (BM * WSTR), src, ct,
                             (ns & 3) * DCH, t);
            }
            const __nv_bfloat16* eS = (step >= 8) ? elo_s : ehi_s;
            const __nv_bfloat16* wS = wbuf + (step & 1) * (BM * WSTR);
            const int dc = (step & 3) * DCH;

            #pragma unroll
            for (int ks = 0; ks < 4; ks++) {
                const int k0 = dc + ks * 16 + lk;
                const int kl = ks * 16 + lk;
                unsigned a[2][4];
                #pragma unroll
                for (int mf = 0; mf < 2; mf++) {
                    int r = wrow * 32 + mf * 16 + lr;
                    a[mf][0] = *(const unsigned*)(eS + r * ESTR + k0);
                    a[mf][1] = *(const unsigned*)(eS + (r + 8) * ESTR + k0);
                    a[mf][2] = *(const unsigned*)(eS + r * ESTR + k0 + 8);
                    a[mf][3] = *(const unsigned*)(eS + (r + 8) * ESTR + k0 + 8);
                }
                #pragma unroll
                for (int nf = 0; nf < 8; nf++) {
                    int c = wcol * 64 + nf * 8 + lr;
                    unsigned b0 = *(const unsigned*)(wS + c * WSTR + kl);
                    unsigned b1 = *(const unsigned*)(wS + c * WSTR + kl + 8);
                    mma_bf16(acc[0][nf], a[0], b0, b1);
                    mma_bf16(acc[1][nf], a[1], b0, b1);
                }
            }
        }

        // ---- epilogue: score + running top-2 ----
        #pragma unroll
        for (int mf = 0; mf < 2; mf++)
        #pragma unroll
        for (int rh = 0; rh < 2; rh++) {
            const int slot = mf * 2 + rh;
            float A = A_s[wrow * 32 + mf * 16 + rh * 8 + lr];
            #pragma unroll
            for (int nf = 0; nf < 8; nf++)
            #pragma unroll
            for (int ci = 0; ci < 2; ci++) {
                int code = ct * BM + wcol * 64 + nf * 8 + (lane & 3) * 2 + ci;
                float dot = acc[mf][nf][rh * 2 + ci];
                float s = __fadd_rn(__fadd_rn(A, -2.0f * dot), nw_s[code]);
                if (s < best[slot] || (s == best[slot] && code < bidx[slot])) {
                    sec[slot]  = best[slot];
                    best[slot] = s; bidx[slot] = code;
                } else if (s < sec[slot]) {
                    sec[slot] = s;
                }
            }
        }
    }

    // ---- cross-lane top-2 merge ----
    #pragma unroll
    for (int slot = 0; slot < 4; slot++) {
        #pragma unroll
        for (int o = 1; o < 4; o <<= 1) {
            float ob = __shfl_xor_sync(0xffffffffu, best[slot], o);
            float os = __shfl_xor_sync(0xffffffffu, sec[slot], o);
            int   oi = __shfl_xor_sync(0xffffffffu, bidx[slot], o);
            if (ob < best[slot] || (ob == best[slot] && oi < bidx[slot])) {
                sec[slot]  = fminf(best[slot], os);
                best[slot] = ob; bidx[slot] = oi;
            } else {
                sec[slot] = fminf(sec[slot], ob);
            }
        }
    }
    if ((lane & 3) == 0) {
        #pragma unroll
        for (int slot = 0; slot < 4; slot++) {
            int mf = slot >> 1, rh = slot & 1;
            int row = wrow * 32 + mf * 16 + rh * 8 + lr;
            rS[row * 2 + wcol] = best[slot];
            rC[row * 2 + wcol] = sec[slot];
            rI[row * 2 + wcol] = bidx[slot];
        }
    }
    __syncthreads();
    if (t < BM) {
        float b0 = rS[t * 2 + 0], b1 = rS[t * 2 + 1];
        float c0 = rC[t * 2 + 0], c1 = rC[t * 2 + 1];
        int   i0 = rI[t * 2 + 0], i1 = rI[t * 2 + 1];
        float fb, fs; int fi;
        if (b1 < b0 || (b1 == b0 && i1 < i0)) {
            fb = b1; fi = i1; fs = fminf(b0, c1);
        } else {
            fb = b0; fi = i0; fs = fminf(c0, b1);
        }
        g_idx[rowbase + t] = fi;
        if (fs - fb < RESCUE_THRESH) {
            int pos = atomicAdd(&g_flagcnt, 1);
            if (pos < NMAX) g_flaglist[pos] = rowbase + t;
        }
    }
}

// ---------------------------------------------------------------------------
// Kernel: exact fp32 rescore of flagged rows, v2.
// Block = 8 flagged rows (warp per row). Codes processed in 32-wide tiles:
// cooperative coalesced stage of 32 w rows into smem, then lane=code computes
// the full 256-d dot from smem (e broadcast, w conflict-free LDS.128).
// No shuffles in the hot loop; one tie-break reduce per row at the end.
// ---------------------------------------------------------------------------
__global__ void __launch_bounds__(256)
vq_rescue(const float* __restrict__ e, const float* __restrict__ w, int K) {
    __shared__ float e_s[8][260];
    __shared__ float w_s[32][260];
    __shared__ float nwt[32];

    const int t    = threadIdx.x;
    const int wid  = t >> 5;
    const int lane = t & 31;
    const int nflag = g_flagcnt;

    for (int base = blockIdx.x * 8; base < nflag; base += gridDim.x * 8) {
        int row = -1;
        if (base + wid < nflag) row = g_flaglist[base + wid];

        if (row >= 0) {
            const float4* src = (const float4*)(e + (size_t)row * D);
            *(float4*)&e_s[wid][lane * 8]     = src[lane * 2];
            *(float4*)&e_s[wid][lane * 8 + 4] = src[lane * 2 + 1];
        }
        float A = (row >= 0) ? g_A[row] : 0.0f;
        float best = FLT_MAX;
        int   bidx = 0;

        for (int ct = 0; ct < K; ct += 32) {
            __syncthreads();
            // stage 32 w rows (32 KB): 2048 float4, 8 per thread, coalesced
            #pragma unroll
            for (int i = 0; i < 8; i++) {
                int id = t + i * 256;           // [0, 2048)
                int c  = id >> 6;               // code within tile
                int v  = (id & 63) * 4;         // float offset
                *(float4*)&w_s[c][v] =
                    __ldg((const float4*)(w + (size_t)(ct + c) * D + v));
            }
            if (t < 32) nwt[t] = g_nw[ct + t];
            __syncthreads();

            if (row >= 0) {
                int c = ct + lane;
                float d0 = 0.f, d1 = 0.f, d2 = 0.f, d3 = 0.f;
                #pragma unroll
                for (int v = 0; v < D; v += 8) {
                    float4 wv0 = *(const float4*)&w_s[lane][v];
                    float4 wv1 = *(const float4*)&w_s[lane][v + 4];
                    float4 ev0 = *(const float4*)&e_s[wid][v];
                    float4 ev1 = *(const float4*)&e_s[wid][v + 4];
                    d0 += ev0.x * wv0.x + ev1.x * wv1.x;
                    d1 += ev0.y * wv0.y + ev1.y * wv1.y;
                    d2 += ev0.z * wv0.z + ev1.z * wv1.z;
                    d3 += ev0.w * wv0.w + ev1.w * wv1.w;
                }
                float dot = (d0 + d1) + (d2 + d3);
                float s = __fadd_rn(__fadd_rn(A, -2.0f * dot), nwt[lane]);
                if (s < best) { best = s; bidx = c; }   // ascending c per lane
            }
        }

        // cross-lane tie-break reduce (codes interleave mod 32; tie -> min idx)
        #pragma unroll
        for (int o = 16; o; o >>= 1) {
            float ob = __shfl_xor_sync(0xffffffffu, best, o);
            int   oi = __shfl_xor_sync(0xffffffffu, bidx, o);
            if (ob < best || (ob == best && oi < bidx)) { best = ob; bidx = oi; }
        }
        if (row >= 0 && lane == 0) g_idx[row] = bidx;
        __syncthreads();   // protect e_s before next batch overwrites
    }
}

// ---------------------------------------------------------------------------
// Kernel: gather quantized rows, write indices, accumulate loss + counts.
// ---------------------------------------------------------------------------
__global__ void vq_gather_kernel(const float* __restrict__ e,
                                 const float* __restrict__ w,
                                 float* __restrict__ out,
                                 long long out_size, int N) {
    __shared__ double bsum[8];
    const int wl   = threadIdx.x >> 5;
    const int lane = threadIdx.x & 31;
    const int row  = blockIdx.x * 8 + wl;

    float ss = 0.0f;
    int idx = 0;
    if (row < N) {
        idx = g_idx[row];
        const float4* qp = (const float4*)(w + (size_t)idx * D);
        const float4* ep = (const float4*)(e + (size_t)row * D);
        float4*       op = (float4*)(out + (size_t)row * D);
        #pragma unroll
        for (int c = 0; c < 2; c++) {
            int i = lane + c * 32;
            float4 q  = __ldg(&qp[i]);
            float4 ev = ep[i];
            op[i] = q;
            float dx = q.x - ev.x, dy = q.y - ev.y;
            float dz = q.z - ev.z, dw = q.w - ev.w;
            ss += dx * dx + dy * dy + dz * dz + dw * dw;
        }
    }
    #pragma unroll
    for (int o = 16; o; o >>= 1) ss += __shfl_xor_sync(0xffffffffu, ss, o);
    if (lane == 0) {
        bsum[wl] = (double)ss;
        if (row < N) {
            atomicAdd(&g_counts[idx], 1u);
            long long p = (long long)N * D + row;
            if (p < out_size) out[p] = (float)idx;
        }
    }
    __syncthreads();
    if (threadIdx.x == 0) {
        double s = 0.0;
        #pragma unroll
        for (int i = 0; i < 8; i++) s += bsum[i];
        atomicAdd(&g_loss, s);
    }
}

// ---------------------------------------------------------------------------
// Kernel: finalize scalars.
// ---------------------------------------------------------------------------
__global__ void vq_finalize_kernel(float* __restrict__ out, long long out_size,
                                   int N, int K) {
    __shared__ unsigned red[1024];
    int t = threadIdx.x;
    unsigned m = (t < K) ? g_counts[t] : 0u;
    red[t] = m;
    __syncthreads();
    #pragma unroll
    for (int s = 512; s; s >>= 1) {
        if (t < s) { unsigned o = red[t + s]; if (o > red[t]) red[t] = o; }
        __syncthreads();
    }
    if (t == 0) {
        long long base = (long long)N * D + N;
        if (base < out_size)
            out[base] = (float)(g_loss / ((double)N * (double)D));
        if (base + 1 < out_size)
            out[base + 1] = (float)red[0] / (float)N;
    }
}

// ---------------------------------------------------------------------------
extern "C" void kernel_launch(void* const* d_in, const int* in_sizes, int n_in,
                              void* d_out, int out_size) {
    const float* e = (const float*)d_in[0];
    const float* w = (const float*)d_in[1];
    float* out = (float*)d_out;

    int N = in_sizes[0] / D;
    int K = in_sizes[1] / D;
    if (N > NMAX) N = NMAX;
    if (K > KMAX) K = KMAX;
    long long osz = (long long)out_size;

    cudaFuncSetAttribute(vq_argmin_mma,
                         cudaFuncAttributeMaxDynamicSharedMemorySize, SMEM_BYTES);

    vq_prep_e<<<(N * 32 + 255) / 256, 256>>>(e, N);
    vq_prep_w<<<(K * 32 + 255) / 256, 256>>>(w, K);
    vq_argmin_mma<<<N / BM, 256, SMEM_BYTES>>>(K);
    vq_rescue<<<256, 256>>>(e, w, K);
    vq_gather_kernel<<<(N + 7) / 8, 256>>>(e, w, out, osz, N);
    vq_finalize_kernel<<<1, 1024>>>(out, osz, N, K);
}

// round 9
// speedup vs baseline: 2.0019x; 1.0675x over previous
#include <cuda_runtime.h>
#include <cuda_bf16.h>
#include <cstdint>
#include <cfloat>

#define D       256
#define KMAX    1024
#define NMAX    65536
#define BM      128
#define ESTR    264     // bf16 stride for e smem tiles
#define WSTR    72      // bf16 stride for w smem chunks
#define DCH     64
#define RESCUE_THRESH 5e-5f
#define RROWS   16      // rescue rows per block

// -------- device scratch (static; no runtime allocation) --------
__device__ __nv_bfloat16 g_ehi[(size_t)NMAX * D];
__device__ __nv_bfloat16 g_elo[(size_t)NMAX * D];
__device__ __nv_bfloat16 g_whi[(size_t)KMAX * D];
__device__ __nv_bfloat16 g_wlo[(size_t)KMAX * D];
__device__ float        g_nw[KMAX];
__device__ float        g_A[NMAX];
__device__ int          g_idx[NMAX];
__device__ unsigned int g_counts[KMAX];
__device__ double       g_loss;
__device__ int          g_flagcnt;
__device__ int          g_flaglist[NMAX];

// smem layout for the mma argmin kernel (bytes): e hi/lo + 3 w buffers + misc
#define SM_EHI_B   (BM * ESTR * 2)
#define SM_WBUF_B  (3 * BM * WSTR * 2)
#define SMEM_BYTES (2 * SM_EHI_B + SM_WBUF_B + BM * 4 + KMAX * 4 \
                    + BM * 2 * 4 + BM * 2 * 4 + BM * 2 * 4)

// rescue smem (dynamic)
#define RS_E_F     (RROWS * 260)
#define RS_W_F     (2 * 32 * 260)
#define RS_SMEM_BYTES ((RS_E_F + RS_W_F + 2 * 32 + RROWS + RROWS) * 4)

// ---------------------------------------------------------------------------
// helpers
// ---------------------------------------------------------------------------
__device__ __forceinline__ void cpa16(void* dst, const void* src) {
    unsigned d = (unsigned)__cvta_generic_to_shared(dst);
    asm volatile("cp.async.cg.shared.global [%0], [%1], 16;\n" :: "r"(d), "l"(src));
}
__device__ __forceinline__ void cpa_commit() {
    asm volatile("cp.async.commit_group;\n");
}
__device__ __forceinline__ void cpa_wait0() {
    asm volatile("cp.async.wait_group 0;\n");
}
__device__ __forceinline__ void cpa_wait1() {
    asm volatile("cp.async.wait_group 1;\n");
}
__device__ __forceinline__ void mma_bf16(float* c, const unsigned* a, unsigned b0, unsigned b1) {
    asm volatile(
        "mma.sync.aligned.m16n8k16.row.col.f32.bf16.bf16.f32 "
        "{%0,%1,%2,%3}, {%4,%5,%6,%7}, {%8,%9}, {%0,%1,%2,%3};\n"
        : "+f"(c[0]), "+f"(c[1]), "+f"(c[2]), "+f"(c[3])
        : "r"(a[0]), "r"(a[1]), "r"(a[2]), "r"(a[3]), "r"(b0), "r"(b1));
}

// ---------------------------------------------------------------------------
// Kernel: convert e -> bf16 hi/lo, compute ||e_row||^2 (fp64 -> fp32).
// ---------------------------------------------------------------------------
__global__ void vq_prep_e(const float* __restrict__ e, int N) {
    int gw   = (blockIdx.x * blockDim.x + threadIdx.x) >> 5;
    int lane = threadIdx.x & 31;
    if (gw >= N) return;
    const float* src = e + (size_t)gw * D + lane * 8;
    float4 v0 = *(const float4*)(src);
    float4 v1 = *(const float4*)(src + 4);
    float x[8] = {v0.x, v0.y, v0.z, v0.w, v1.x, v1.y, v1.z, v1.w};
    double s = 0.0;
    unsigned hi[4], lo[4];
    #pragma unroll
    for (int i = 0; i < 4; i++) {
        float a = x[2*i], b = x[2*i+1];
        s += (double)a * a + (double)b * b;
        __nv_bfloat16 ha = __float2bfloat16_rn(a);
        __nv_bfloat16 hb = __float2bfloat16_rn(b);
        __nv_bfloat16 la = __float2bfloat16_rn(a - __bfloat162float(ha));
        __nv_bfloat16 lb = __float2bfloat16_rn(b - __bfloat162float(hb));
        hi[i] = (unsigned)__bfloat16_as_ushort(ha) | ((unsigned)__bfloat16_as_ushort(hb) << 16);
        lo[i] = (unsigned)__bfloat16_as_ushort(la) | ((unsigned)__bfloat16_as_ushort(lb) << 16);
    }
    *(uint4*)(g_ehi + (size_t)gw * D + lane * 8) = make_uint4(hi[0], hi[1], hi[2], hi[3]);
    *(uint4*)(g_elo + (size_t)gw * D + lane * 8) = make_uint4(lo[0], lo[1], lo[2], lo[3]);
    #pragma unroll
    for (int o = 16; o; o >>= 1) s += __shfl_xor_sync(0xffffffffu, s, o);
    if (lane == 0) g_A[gw] = (float)s;
}

// ---------------------------------------------------------------------------
// Kernel: convert w -> bf16 hi/lo, ||w_k||^2, zero counts/loss/flags.
// ---------------------------------------------------------------------------
__global__ void vq_prep_w(const float* __restrict__ w, int K) {
    int gid  = blockIdx.x * blockDim.x + threadIdx.x;
    int gw   = gid >> 5;
    int lane = threadIdx.x & 31;
    if (gid < K)  g_counts[gid] = 0u;
    if (gid == 0) { g_loss = 0.0; g_flagcnt = 0; }
    if (gw >= K) return;
    const float* src = w + (size_t)gw * D + lane * 8;
    float4 v0 = *(const float4*)(src);
    float4 v1 = *(const float4*)(src + 4);
    float x[8] = {v0.x, v0.y, v0.z, v0.w, v1.x, v1.y, v1.z, v1.w};
    double s = 0.0;
    unsigned hi[4], lo[4];
    #pragma unroll
    for (int i = 0; i < 4; i++) {
        float a = x[2*i], b = x[2*i+1];
        s += (double)a * a + (double)b * b;
        __nv_bfloat16 ha = __float2bfloat16_rn(a);
        __nv_bfloat16 hb = __float2bfloat16_rn(b);
        __nv_bfloat16 la = __float2bfloat16_rn(a - __bfloat162float(ha));
        __nv_bfloat16 lb = __float2bfloat16_rn(b - __bfloat162float(hb));
        hi[i] = (unsigned)__bfloat16_as_ushort(ha) | ((unsigned)__bfloat16_as_ushort(hb) << 16);
        lo[i] = (unsigned)__bfloat16_as_ushort(la) | ((unsigned)__bfloat16_as_ushort(lb) << 16);
    }
    *(uint4*)(g_whi + (size_t)gw * D + lane * 8) = make_uint4(hi[0], hi[1], hi[2], hi[3]);
    *(uint4*)(g_wlo + (size_t)gw * D + lane * 8) = make_uint4(lo[0], lo[1], lo[2], lo[3]);
    #pragma unroll
    for (int o = 16; o; o >>= 1) s += __shfl_xor_sync(0xffffffffu, s, o);
    if (lane == 0) g_nw[gw] = (float)s;
}

// ---------------------------------------------------------------------------
// Kernel: fused split-bf16 HMMA GEMM + top-2 argmin + near-tie flagging.
// 96 flattened steps (8 ct x [hh x4, hl x4, lh x4]); 3-buffer cp.async
// pipeline with depth 2 (wait_group <= 1) so each step's L2 latency is hidden.
// Numerics identical to round 4/5 (same mma order, same epilogue).
// ---------------------------------------------------------------------------
__device__ __forceinline__ void issue_w_step(__nv_bfloat16* wbuf, int buf,
                                             int ct, int sub, int t) {
    const __nv_bfloat16* src = ((sub >> 2) == 1) ? g_wlo : g_whi;
    __nv_bfloat16* dst = wbuf + buf * (BM * WSTR);
    int dc = (sub & 3) * DCH;
    #pragma unroll
    for (int i = 0; i < 4; i++) {
        int id = t + i * 256;
        int code = id >> 3;
        int dcol = (id & 7) * 8;
        cpa16(dst + code * WSTR + dcol,
              src + (size_t)(ct * BM + code) * D + dc + dcol);
    }
    cpa_commit();
}

__global__ void __launch_bounds__(256, 1)
vq_argmin_mma(int K) {
    extern __shared__ char smraw[];
    __nv_bfloat16* ehi_s = (__nv_bfloat16*)smraw;
    __nv_bfloat16* elo_s = ehi_s + BM * ESTR;
    __nv_bfloat16* wbuf  = elo_s + BM * ESTR;        // 3 buffers of BM*WSTR
    float* A_s  = (float*)(wbuf + 3 * BM * WSTR);
    float* nw_s = A_s + BM;
    float* rS   = nw_s + KMAX;
    float* rC   = rS + BM * 2;
    int*   rI   = (int*)(rC + BM * 2);

    const int t    = threadIdx.x;
    const int lane = t & 31;
    const int wid  = t >> 5;
    const int wrow = wid >> 1;
    const int wcol = wid & 1;
    const int rowbase = blockIdx.x * BM;
    const int lr = lane >> 2;
    const int lk = (lane & 3) * 2;

    {
        const __nv_bfloat16* sh = g_ehi + (size_t)rowbase * D;
        const __nv_bfloat16* sl = g_elo + (size_t)rowbase * D;
        #pragma unroll
        for (int i = 0; i < 16; i++) {
            int id = t + i * 256;
            int r = id >> 5, dc = (id & 31) * 8;
            *(uint4*)(ehi_s + r * ESTR + dc) = *(const uint4*)(sh + r * D + dc);
            *(uint4*)(elo_s + r * ESTR + dc) = *(const uint4*)(sl + r * D + dc);
        }
    }
    if (t < BM) A_s[t] = g_A[rowbase + t];
    #pragma unroll
    for (int i = 0; i < 4; i++) nw_s[t + i * 256] = g_nw[t + i * 256];
    __syncthreads();

    float best[4], sec[4];
    int   bidx[4];
    #pragma unroll
    for (int i = 0; i < 4; i++) { best[i] = FLT_MAX; sec[i] = FLT_MAX; bidx[i] = 0; }

    const int NCT = K / BM;                          // 8

    // pipeline prologue: steps 0 and 1 in flight
    issue_w_step(wbuf, 0, 0, 0, t);
    issue_w_step(wbuf, 1, 0, 1, t);

    int bufc = 0;                                    // compute buffer = g % 3
    for (int ct = 0; ct < NCT; ct++) {
        float acc[2][8][4];
        #pragma unroll
        for (int mf = 0; mf < 2; mf++)
            #pragma unroll
            for (int nf = 0; nf < 8; nf++)
                #pragma unroll
                for (int v = 0; v < 4; v++) acc[mf][nf][v] = 0.0f;

        #pragma unroll
        for (int sub = 0; sub < 12; sub++) {
            const bool last2 = (ct == NCT - 1) && (sub >= 10);
            if ((ct == NCT - 1) && (sub == 11)) cpa_wait0();
            else                                cpa_wait1();
            __syncthreads();
            if (!last2) {
                int sub2 = sub + 2, ct2 = ct;
                if (sub2 >= 12) { sub2 -= 12; ct2++; }
                int bufi = bufc + 2; if (bufi >= 3) bufi -= 3;
                issue_w_step(wbuf, bufi, ct2, sub2, t);
            }
            const __nv_bfloat16* eS = (sub >= 8) ? elo_s : ehi_s;
            const __nv_bfloat16* wS = wbuf + bufc * (BM * WSTR);
            const int dc = (sub & 3) * DCH;

            #pragma unroll
            for (int ks = 0; ks < 4; ks++) {
                const int k0 = dc + ks * 16 + lk;
                const int kl = ks * 16 + lk;
                unsigned a[2][4];
                #pragma unroll
                for (int mf = 0; mf < 2; mf++) {
                    int r = wrow * 32 + mf * 16 + lr;
                    a[mf][0] = *(const unsigned*)(eS + r * ESTR + k0);
                    a[mf][1] = *(const unsigned*)(eS + (r + 8) * ESTR + k0);
                    a[mf][2] = *(const unsigned*)(eS + r * ESTR + k0 + 8);
                    a[mf][3] = *(const unsigned*)(eS + (r + 8) * ESTR + k0 + 8);
                }
                #pragma unroll
                for (int nf = 0; nf < 8; nf++) {
                    int c = wcol * 64 + nf * 8 + lr;
                    unsigned b0 = *(const unsigned*)(wS + c * WSTR + kl);
                    unsigned b1 = *(const unsigned*)(wS + c * WSTR + kl + 8);
                    mma_bf16(acc[0][nf], a[0], b0, b1);
                    mma_bf16(acc[1][nf], a[1], b0, b1);
                }
            }
            bufc++; if (bufc >= 3) bufc = 0;
        }

        // ---- epilogue: score + running top-2 ----
        #pragma unroll
        for (int mf = 0; mf < 2; mf++)
        #pragma unroll
        for (int rh = 0; rh < 2; rh++) {
            const int slot = mf * 2 + rh;
            float A = A_s[wrow * 32 + mf * 16 + rh * 8 + lr];
            #pragma unroll
            for (int nf = 0; nf < 8; nf++)
            #pragma unroll
            for (int ci = 0; ci < 2; ci++) {
                int code = ct * BM + wcol * 64 + nf * 8 + (lane & 3) * 2 + ci;
                float dot = acc[mf][nf][rh * 2 + ci];
                float s = __fadd_rn(__fadd_rn(A, -2.0f * dot), nw_s[code]);
                if (s < best[slot] || (s == best[slot] && code < bidx[slot])) {
                    sec[slot]  = best[slot];
                    best[slot] = s; bidx[slot] = code;
                } else if (s < sec[slot]) {
                    sec[slot] = s;
                }
            }
        }
    }

    // ---- cross-lane top-2 merge ----
    #pragma unroll
    for (int slot = 0; slot < 4; slot++) {
        #pragma unroll
        for (int o = 1; o < 4; o <<= 1) {
            float ob = __shfl_xor_sync(0xffffffffu, best[slot], o);
            float os = __shfl_xor_sync(0xffffffffu, sec[slot], o);
            int   oi = __shfl_xor_sync(0xffffffffu, bidx[slot], o);
            if (ob < best[slot] || (ob == best[slot] && oi < bidx[slot])) {
                sec[slot]  = fminf(best[slot], os);
                best[slot] = ob; bidx[slot] = oi;
            } else {
                sec[slot] = fminf(sec[slot], ob);
            }
        }
    }
    if ((lane & 3) == 0) {
        #pragma unroll
        for (int slot = 0; slot < 4; slot++) {
            int mf = slot >> 1, rh = slot & 1;
            int row = wrow * 32 + mf * 16 + rh * 8 + lr;
            rS[row * 2 + wcol] = best[slot];
            rC[row * 2 + wcol] = sec[slot];
            rI[row * 2 + wcol] = bidx[slot];
        }
    }
    __syncthreads();
    if (t < BM) {
        float b0 = rS[t * 2 + 0], b1 = rS[t * 2 + 1];
        float c0 = rC[t * 2 + 0], c1 = rC[t * 2 + 1];
        int   i0 = rI[t * 2 + 0], i1 = rI[t * 2 + 1];
        float fb, fs; int fi;
        if (b1 < b0 || (b1 == b0 && i1 < i0)) {
            fb = b1; fi = i1; fs = fminf(b0, c1);
        } else {
            fb = b0; fi = i0; fs = fminf(c0, b1);
        }
        g_idx[rowbase + t] = fi;
        if (fs - fb < RESCUE_THRESH) {
            int pos = atomicAdd(&g_flagcnt, 1);
            if (pos < NMAX) g_flaglist[pos] = rowbase + t;
        }
    }
}

// ---------------------------------------------------------------------------
// Kernel: exact fp32 rescore of flagged rows, v3.
// 16 rows per block (2 per warp). Codes in 32-wide tiles; w tiles staged via
// double-buffered cp.async (overlaps L2 latency with compute). lane = code.
// Scoring identical to v2 (fp32 dot, s = (A - 2dot) + nw, first-index ties).
// ---------------------------------------------------------------------------
__global__ void __launch_bounds__(256)
vq_rescue(const float* __restrict__ e, const float* __restrict__ w, int K) {
    extern __shared__ float rsm[];
    float* e_s  = rsm;                          // [RROWS][260]
    float* w_s  = e_s + RS_E_F;                 // [2][32][260]
    float* nwt  = w_s + RS_W_F;                 // [2][32]
    float* aA   = nwt + 64;                     // [RROWS]
    int*   rows = (int*)(aA + RROWS);           // [RROWS]

    const int t    = threadIdx.x;
    const int wid  = t >> 5;
    const int lane = t & 31;
    const int nflag = g_flagcnt;
    const int NT = K / 32;                      // 32 tiles

    for (int base = blockIdx.x * RROWS; base < nflag; base += gridDim.x * RROWS) {
        if (t < RROWS) {
            int s = base + t;
            int r = (s < nflag) ? g_flaglist[s] : -1;
            rows[t] = r;
            aA[t]   = (r >= 0) ? g_A[r] : 0.0f;
        }
        __syncthreads();
        // stage 16 e rows: 1024 float4, 4 per thread
        #pragma unroll
        for (int i = 0; i < 4; i++) {
            int id = t + i * 256;
            int r  = id >> 6;
            int v  = (id & 63) * 4;
            int rw = rows[r];
            if (rw >= 0)
                *(float4*)&e_s[r * 260 + v] =
                    __ldg((const float4*)(e + (size_t)rw * D + v));
        }

        // w pipeline prologue: tile 0 into buf 0
        #pragma unroll
        for (int i = 0; i < 8; i++) {
            int id = t + i * 256;
            int c  = id >> 6;
            int v  = (id & 63) * 4;
            cpa16(&w_s[c * 260 + v], w + (size_t)c * D + v);
        }
        cpa_commit();
        if (t < 32) nwt[t] = g_nw[t];

        const int r0 = wid * 2, r1 = wid * 2 + 1;
        const int rw0 = rows[r0], rw1 = rows[r1];
        const float A0 = aA[r0], A1 = aA[r1];
        float best0 = FLT_MAX, best1 = FLT_MAX;
        int   bi0 = 0, bi1 = 0;

        for (int tile = 0; tile < NT; tile++) {
            const int buf = tile & 1;
            cpa_wait0();
            __syncthreads();
            if (tile < NT - 1) {
                const int nb = buf ^ 1;
                #pragma unroll
                for (int i = 0; i < 8; i++) {
                    int id = t + i * 256;
                    int c  = id >> 6;
                    int v  = (id & 63) * 4;
                    cpa16(&w_s[nb * 32 * 260 + c * 260 + v],
                          w + (size_t)((tile + 1) * 32 + c) * D + v);
                }
                cpa_commit();
                if (t < 32) nwt[(buf ^ 1) * 32 + t] = g_nw[(tile + 1) * 32 + t];
            }

            const float* wrow = &w_s[buf * 32 * 260 + lane * 260];
            float a0 = 0.f, a1 = 0.f, a2 = 0.f, a3 = 0.f;
            float c0 = 0.f, c1 = 0.f, c2 = 0.f, c3 = 0.f;
            #pragma unroll
            for (int v = 0; v < D; v += 8) {
                float4 wv0 = *(const float4*)&wrow[v];
                float4 wv1 = *(const float4*)&wrow[v + 4];
                float4 e00 = *(const float4*)&e_s[r0 * 260 + v];
                float4 e01 = *(const float4*)&e_s[r0 * 260 + v + 4];
                a0 += e00.x * wv0.x + e01.x * wv1.x;
                a1 += e00.y * wv0.y + e01.y * wv1.y;
                a2 += e00.z * wv0.z + e01.z * wv1.z;
                a3 += e00.w * wv0.w + e01.w * wv1.w;
                float4 e10 = *(const float4*)&e_s[r1 * 260 + v];
                float4 e11 = *(const float4*)&e_s[r1 * 260 + v + 4];
                c0 += e10.x * wv0.x + e11.x * wv1.x;
                c1 += e10.y * wv0.y + e11.y * wv1.y;
                c2 += e10.z * wv0.z + e11.z * wv1.z;
                c3 += e10.w * wv0.w + e11.w * wv1.w;
            }
            float nv = nwt[buf * 32 + lane];
            int code = tile * 32 + lane;
            float dot0 = (a0 + a1) + (a2 + a3);
            float dot1 = (c0 + c1) + (c2 + c3);
            float s0 = __fadd_rn(__fadd_rn(A0, -2.0f * dot0), nv);
            float s1 = __fadd_rn(__fadd_rn(A1, -2.0f * dot1), nv);
            if (s0 < best0) { best0 = s0; bi0 = code; }   // ascending code per lane
            if (s1 < best1) { best1 = s1; bi1 = code; }
        }

        // cross-lane tie-break reduce
        #pragma unroll
        for (int o = 16; o; o >>= 1) {
            float ob = __shfl_xor_sync(0xffffffffu, best0, o);
            int   oi = __shfl_xor_sync(0xffffffffu, bi0, o);
            if (ob < best0 || (ob == best0 && oi < bi0)) { best0 = ob; bi0 = oi; }
            float pb = __shfl_xor_sync(0xffffffffu, best1, o);
            int   pi = __shfl_xor_sync(0xffffffffu, bi1, o);
            if (pb < best1 || (pb == best1 && pi < bi1)) { best1 = pb; bi1 = pi; }
        }
        if (lane == 0) {
            if (rw0 >= 0) g_idx[rw0] = bi0;
            if (rw1 >= 0) g_idx[rw1] = bi1;
        }
        __syncthreads();   // protect e_s / rows before next batch
    }
}

// ---------------------------------------------------------------------------
// Kernel: gather quantized rows, write indices, accumulate loss + counts.
// ---------------------------------------------------------------------------
__global__ void vq_gather_kernel(const float* __restrict__ e,
                                 const float* __restrict__ w,
                                 float* __restrict__ out,
                                 long long out_size, int N) {
    __shared__ double bsum[8];
    const int wl   = threadIdx.x >> 5;
    const int lane = threadIdx.x & 31;
    const int row  = blockIdx.x * 8 + wl;

    float ss = 0.0f;
    int idx = 0;
    if (row < N) {
        idx = g_idx[row];
        const float4* qp = (const float4*)(w + (size_t)idx * D);
        const float4* ep = (const float4*)(e + (size_t)row * D);
        float4*       op = (float4*)(out + (size_t)row * D);
        #pragma unroll
        for (int c = 0; c < 2; c++) {
            int i = lane + c * 32;
            float4 q  = __ldg(&qp[i]);
            float4 ev = ep[i];
            op[i] = q;
            float dx = q.x - ev.x, dy = q.y - ev.y;
            float dz = q.z - ev.z, dw = q.w - ev.w;
            ss += dx * dx + dy * dy + dz * dz + dw * dw;
        }
    }
    #pragma unroll
    for (int o = 16; o; o >>= 1) ss += __shfl_xor_sync(0xffffffffu, ss, o);
    if (lane == 0) {
        bsum[wl] = (double)ss;
        if (row < N) {
            atomicAdd(&g_counts[idx], 1u);
            long long p = (long long)N * D + row;
            if (p < out_size) out[p] = (float)idx;
        }
    }
    __syncthreads();
    if (threadIdx.x == 0) {
        double s = 0.0;
        #pragma unroll
        for (int i = 0; i < 8; i++) s += bsum[i];
        atomicAdd(&g_loss, s);
    }
}

// ---------------------------------------------------------------------------
// Kernel: finalize scalars.
// ---------------------------------------------------------------------------
__global__ void vq_finalize_kernel(float* __restrict__ out, long long out_size,
                                   int N, int K) {
    __shared__ unsigned red[1024];
    int t = threadIdx.x;
    unsigned m = (t < K) ? g_counts[t] : 0u;
    red[t] = m;
    __syncthreads();
    #pragma unroll
    for (int s = 512; s; s >>= 1) {
        if (t < s) { unsigned o = red[t + s]; if (o > red[t]) red[t] = o; }
        __syncthreads();
    }
    if (t == 0) {
        long long base = (long long)N * D + N;
        if (base < out_size)
            out[base] = (float)(g_loss / ((double)N * (double)D));
        if (base + 1 < out_size)
            out[base + 1] = (float)red[0] / (float)N;
    }
}

// ---------------------------------------------------------------------------
extern "C" void kernel_launch(void* const* d_in, const int* in_sizes, int n_in,
                              void* d_out, int out_size) {
    const float* e = (const float*)d_in[0];
    const float* w = (const float*)d_in[1];
    float* out = (float*)d_out;

    int N = in_sizes[0] / D;
    int K = in_sizes[1] / D;
    if (N > NMAX) N = NMAX;
    if (K > KMAX) K = KMAX;
    long long osz = (long long)out_size;

    cudaFuncSetAttribute(vq_argmin_mma,
                         cudaFuncAttributeMaxDynamicSharedMemorySize, SMEM_BYTES);
    cudaFuncSetAttribute(vq_rescue,
                         cudaFuncAttributeMaxDynamicSharedMemorySize, RS_SMEM_BYTES);

    vq_prep_e<<<(N * 32 + 255) / 256, 256>>>(e, N);
    vq_prep_w<<<(K * 32 + 255) / 256, 256>>>(w, K);
    vq_argmin_mma<<<N / BM, 256, SMEM_BYTES>>>(K);
    vq_rescue<<<256, 256, RS_SMEM_BYTES>>>(e, w, K);
    vq_gather_kernel<<<(N + 7) / 8, 256>>>(e, w, out, osz, N);
    vq_finalize_kernel<<<1, 1024>>>(out, osz, N, K);
}